// round 2
// baseline (speedup 1.0000x reference)
#include <cuda_runtime.h>
#include <math.h>

// ------------------------------------------------------------------
// Problem constants
// ------------------------------------------------------------------
#define B_    4
#define C_    256
#define H_    128
#define W_    128
#define HW    (H_*W_)          // 16384
#define NTOK  (B_*HW)          // 65536
#define CB    128
#define HEADS 2
#define CD    64
#define SCALE 0.08838834764831845f   // (256/2)^-0.5
#define EPS   1e-4f

// ------------------------------------------------------------------
// Scratch (static __device__, no allocation)
// ------------------------------------------------------------------
__device__ float g_xn [(size_t)NTOK * C_];        //  64 MB  ln output, [t][c]
__device__ float g_qkv[(size_t)NTOK * 3 * C_];    // 192 MB  [t][768]
__device__ float g_xc [(size_t)NTOK * C_];        //  64 MB  attn+lepe, [t][c]

// token index of window element s for (branch, win)
__device__ __forceinline__ int win_token(int br, int win, int s) {
    int b  = win >> 5;      // win / 32
    int wi = win & 31;
    int y, x;
    if (br == 0) { y = s >> 2;               x = (wi << 2) + (s & 3); }   // 128x4 strip
    else         { y = (wi << 2) + (s >> 7); x = s & 127; }               // 4x128 strip
    return b * HW + y * W_ + x;
}

// ------------------------------------------------------------------
// 1) LayerNorm: x [B,C,H,W] -> g_xn [t][c]
// ------------------------------------------------------------------
__global__ void __launch_bounds__(256) ln_kernel(const float* __restrict__ x,
                                                 const float* __restrict__ gam,
                                                 const float* __restrict__ bet) {
    __shared__ float xs[C_][33];
    __shared__ float mu_s[32], rs_s[32];
    int tid = threadIdx.x;
    int tx = tid & 31, ty = tid >> 5;
    int t0 = blockIdx.x * 32;
    int b  = t0 / HW;
    int pp = t0 - b * HW;
    const float* xb = x + (size_t)b * C_ * HW + pp + tx;
    #pragma unroll
    for (int c = ty; c < C_; c += 8)
        xs[c][tx] = xb[(size_t)c * HW];
    __syncthreads();
    if (tid < 32) {
        float s = 0.f, s2 = 0.f;
        #pragma unroll 8
        for (int c = 0; c < C_; c++) { float v = xs[c][tid]; s += v; s2 += v * v; }
        float mu  = s * (1.0f / C_);
        float var = s2 * (1.0f / C_) - mu * mu;
        mu_s[tid] = mu;
        rs_s[tid] = rsqrtf(var + EPS);
    }
    __syncthreads();
    for (int idx = tid; idx < 32 * C_; idx += 256) {
        int c = idx & 255, tk = idx >> 8;
        g_xn[(size_t)(t0 + tk) * C_ + c] =
            (xs[c][tk] - mu_s[tk]) * rs_s[tk] * gam[c] + bet[c];
    }
}

// ------------------------------------------------------------------
// 2) QKV GEMM: g_qkv[m][n] = sum_k g_xn[m][k] * W[k][n]   (M=65536,N=768,K=256)
// ------------------------------------------------------------------
__global__ void __launch_bounds__(256) gemm_qkv(const float* __restrict__ Bw) {
    __shared__ float As[8][128];
    __shared__ float Bs[8][128];
    int tid = threadIdx.x;
    int m0 = blockIdx.y * 128;
    int n0 = blockIdx.x * 128;
    int tx = tid & 15, ty = tid >> 4;
    float acc[8][8] = {};
    int arow = tid >> 1;
    int akq  = (tid & 1) * 4;
    int brow = tid >> 5;
    int bcol = (tid & 31) * 4;
    const float* Aptr = g_xn + (size_t)(m0 + arow) * C_ + akq;
    const float* Bptr = Bw + (size_t)brow * 768 + n0 + bcol;
    for (int k0 = 0; k0 < 256; k0 += 8) {
        float4 av = *(const float4*)(Aptr + k0);
        As[akq + 0][arow] = av.x; As[akq + 1][arow] = av.y;
        As[akq + 2][arow] = av.z; As[akq + 3][arow] = av.w;
        *(float4*)&Bs[brow][bcol] = *(const float4*)(Bptr + (size_t)k0 * 768);
        __syncthreads();
        #pragma unroll
        for (int k = 0; k < 8; k++) {
            float a[8], bb[8];
            #pragma unroll
            for (int i = 0; i < 8; i++) a[i]  = As[k][ty * 8 + i];
            #pragma unroll
            for (int j = 0; j < 8; j++) bb[j] = Bs[k][tx + j * 16];
            #pragma unroll
            for (int i = 0; i < 8; i++)
                #pragma unroll
                for (int j = 0; j < 8; j++)
                    acc[i][j] += a[i] * bb[j];
        }
        __syncthreads();
    }
    float* Cp = g_qkv + (size_t)m0 * 768 + n0;
    #pragma unroll
    for (int i = 0; i < 8; i++) {
        int m = ty * 8 + i;
        #pragma unroll
        for (int j = 0; j < 8; j++)
            Cp[(size_t)m * 768 + tx + j * 16] = acc[i][j];
    }
}

// ------------------------------------------------------------------
// 3) LePE depthwise 3x3 per strip window -> g_xc (initializes it)
//    conv channel cc maps directly to qkv v-column 512 + br*128 + cc
// ------------------------------------------------------------------
__global__ void lepe_kernel(const float* __restrict__ w1, const float* __restrict__ b1,
                            const float* __restrict__ w2, const float* __restrict__ b2) {
    int cc  = threadIdx.x;                                  // 0..127
    int s   = blockIdx.x * blockDim.y + threadIdx.y;        // 0..511
    int win = blockIdx.y;                                   // 0..127
    int br  = blockIdx.z;                                   // 0..1
    const float* w = (br == 0 ? w1 : w2) + cc * 9;
    float bias = (br == 0 ? b1 : b2)[cc];
    int hsp = (br == 0) ? 128 : 4;
    int wsp = (br == 0) ? 4   : 128;
    int i = s / wsp, j = s % wsp;
    float acc = bias;
    #pragma unroll
    for (int ki = 0; ki < 3; ki++) {
        int ii = i + ki - 1;
        if (ii < 0 || ii >= hsp) continue;
        #pragma unroll
        for (int kj = 0; kj < 3; kj++) {
            int jj = j + kj - 1;
            if (jj < 0 || jj >= wsp) continue;
            int tn = win_token(br, win, ii * wsp + jj);
            acc += w[ki * 3 + kj] * g_qkv[(size_t)tn * 768 + 512 + br * 128 + cc];
        }
    }
    int t = win_token(br, win, s);
    g_xc[(size_t)t * C_ + br * 128 + cc] = acc;
}

// ------------------------------------------------------------------
// 4) Attention: per (branch, win, head, q-tile of 64). Full 64x512 score
//    rows held in SMEM; softmax; PV; accumulate into g_xc (on top of LePE).
// ------------------------------------------------------------------
extern __shared__ float sm_attn[];
__global__ void __launch_bounds__(256) attn_kernel() {
    float* S  = sm_attn;               // [64][513]
    float* Qs = S + 64 * 513;          // [64][65]
    float* KV = Qs + 64 * 65;          // [64][65]
    int qt   = blockIdx.x;             // 0..7
    int head = blockIdx.y;             // 0..1
    int wb   = blockIdx.z;             // 0..255
    int br   = wb >> 7;
    int win  = wb & 127;
    int tid = threadIdx.x;
    int tx = tid & 15, ty = tid >> 4;
    int cbase = br * 128 + head;       // q/k/v column base, stride 2 over d

    // Q tile (pre-scaled)
    for (int idx = tid; idx < 64 * 64; idx += 256) {
        int r = idx >> 6, d = idx & 63;
        int t = win_token(br, win, qt * 64 + r);
        Qs[r * 65 + d] = g_qkv[(size_t)t * 768 + cbase + 2 * d] * SCALE;
    }

    // S = Q K^T
    for (int kt = 0; kt < 8; kt++) {
        __syncthreads();
        for (int idx = tid; idx < 64 * 64; idx += 256) {
            int r = idx >> 6, d = idx & 63;
            int t = win_token(br, win, kt * 64 + r);
            KV[r * 65 + d] = g_qkv[(size_t)t * 768 + 256 + cbase + 2 * d];
        }
        __syncthreads();
        float s4[4][4] = {};
        #pragma unroll
        for (int d = 0; d < 64; d++) {
            float qv[4], kv[4];
            #pragma unroll
            for (int i = 0; i < 4; i++) qv[i] = Qs[(ty * 4 + i) * 65 + d];
            #pragma unroll
            for (int j = 0; j < 4; j++) kv[j] = KV[(tx * 4 + j) * 65 + d];
            #pragma unroll
            for (int i = 0; i < 4; i++)
                #pragma unroll
                for (int j = 0; j < 4; j++)
                    s4[i][j] += qv[i] * kv[j];
        }
        #pragma unroll
        for (int i = 0; i < 4; i++)
            #pragma unroll
            for (int j = 0; j < 4; j++)
                S[(ty * 4 + i) * 513 + kt * 64 + tx * 4 + j] = s4[i][j];
    }
    __syncthreads();

    // softmax over 512 keys, one warp per 8 rows
    int wid = tid >> 5, lane = tid & 31;
    for (int r = wid * 8; r < wid * 8 + 8; r++) {
        float* row = S + r * 513;
        float m = -1e30f;
        for (int c = lane; c < 512; c += 32) m = fmaxf(m, row[c]);
        #pragma unroll
        for (int o = 16; o; o >>= 1) m = fmaxf(m, __shfl_xor_sync(0xffffffffu, m, o));
        float ssum = 0.f;
        for (int c = lane; c < 512; c += 32) {
            float e = __expf(row[c] - m);
            row[c] = e;
            ssum += e;
        }
        #pragma unroll
        for (int o = 16; o; o >>= 1) ssum += __shfl_xor_sync(0xffffffffu, ssum, o);
        float inv = 1.0f / ssum;
        for (int c = lane; c < 512; c += 32) row[c] *= inv;
    }

    // O = P V
    float o4[4][4] = {};
    for (int vt = 0; vt < 8; vt++) {
        __syncthreads();
        for (int idx = tid; idx < 64 * 64; idx += 256) {
            int r = idx >> 6, d = idx & 63;
            int t = win_token(br, win, vt * 64 + r);
            KV[r * 65 + d] = g_qkv[(size_t)t * 768 + 512 + cbase + 2 * d];
        }
        __syncthreads();
        #pragma unroll
        for (int sk = 0; sk < 64; sk++) {
            float pv[4], vv[4];
            #pragma unroll
            for (int i = 0; i < 4; i++) pv[i] = S[(ty * 4 + i) * 513 + vt * 64 + sk];
            #pragma unroll
            for (int j = 0; j < 4; j++) vv[j] = KV[sk * 65 + tx * 4 + j];
            #pragma unroll
            for (int i = 0; i < 4; i++)
                #pragma unroll
                for (int j = 0; j < 4; j++)
                    o4[i][j] += pv[i] * vv[j];
        }
    }

    // accumulate on top of LePE (disjoint elements per block)
    #pragma unroll
    for (int i = 0; i < 4; i++) {
        int t = win_token(br, win, qt * 64 + ty * 4 + i);
        #pragma unroll
        for (int j = 0; j < 4; j++) {
            int d = tx * 4 + j;
            size_t idx = (size_t)t * C_ + br * 128 + 2 * d + head;
            g_xc[idx] += o4[i][j];
        }
    }
}

// ------------------------------------------------------------------
// 5) Proj GEMM: out[b,o,y,x] = sum_c g_xc[t][c] * proj_w[o][c] + proj_b[o]
//    M = tokens (65536), N = 256, K = 256, B transposed, channel-major output
// ------------------------------------------------------------------
__global__ void __launch_bounds__(256) gemm_proj(const float* __restrict__ Pw,
                                                 const float* __restrict__ Pb,
                                                 float* __restrict__ out) {
    __shared__ float As[8][128];
    __shared__ float Bs[8][129];
    int tid = threadIdx.x;
    int m0 = blockIdx.y * 128;
    int n0 = blockIdx.x * 128;
    int tx = tid & 15, ty = tid >> 4;
    float acc[8][8] = {};   // acc[i][j]: m = tx + i*16, n = ty*8 + j
    int arow = tid >> 1;
    int akq  = (tid & 1) * 4;
    const float* Aptr = g_xc + (size_t)(m0 + arow) * C_ + akq;
    int bn  = tid >> 1;
    int bkq = (tid & 1) * 4;
    const float* Bptr = Pw + (size_t)(n0 + bn) * C_ + bkq;
    for (int k0 = 0; k0 < 256; k0 += 8) {
        float4 av = *(const float4*)(Aptr + k0);
        As[akq + 0][arow] = av.x; As[akq + 1][arow] = av.y;
        As[akq + 2][arow] = av.z; As[akq + 3][arow] = av.w;
        float4 bv = *(const float4*)(Bptr + k0);
        Bs[bkq + 0][bn] = bv.x; Bs[bkq + 1][bn] = bv.y;
        Bs[bkq + 2][bn] = bv.z; Bs[bkq + 3][bn] = bv.w;
        __syncthreads();
        #pragma unroll
        for (int k = 0; k < 8; k++) {
            float a[8], bb[8];
            #pragma unroll
            for (int i = 0; i < 8; i++) a[i]  = As[k][tx + i * 16];
            #pragma unroll
            for (int j = 0; j < 8; j++) bb[j] = Bs[k][ty * 8 + j];
            #pragma unroll
            for (int i = 0; i < 8; i++)
                #pragma unroll
                for (int j = 0; j < 8; j++)
                    acc[i][j] += a[i] * bb[j];
        }
        __syncthreads();
    }
    int b  = m0 / HW;
    int pp = m0 - b * HW;
    float* Op = out + (size_t)b * C_ * HW + pp;
    #pragma unroll
    for (int j = 0; j < 8; j++) {
        int o = n0 + ty * 8 + j;
        float bias = Pb[o];
        #pragma unroll
        for (int i = 0; i < 8; i++)
            Op[(size_t)o * HW + tx + i * 16] = acc[i][j] + bias;
    }
}

// ------------------------------------------------------------------
// launch
// ------------------------------------------------------------------
extern "C" void kernel_launch(void* const* d_in, const int* in_sizes, int n_in,
                              void* d_out, int out_size) {
    const float* x       = (const float*)d_in[0];
    const float* ln_g    = (const float*)d_in[1];
    const float* ln_b    = (const float*)d_in[2];
    const float* w_qkv   = (const float*)d_in[3];
    const float* lepe_w1 = (const float*)d_in[4];
    const float* lepe_b1 = (const float*)d_in[5];
    const float* lepe_w2 = (const float*)d_in[6];
    const float* lepe_b2 = (const float*)d_in[7];
    const float* proj_w  = (const float*)d_in[8];
    const float* proj_b  = (const float*)d_in[9];
    float* out = (float*)d_out;

    size_t smem_attn = (size_t)(64 * 513 + 2 * 64 * 65) * sizeof(float);  // 164,608 B
    cudaFuncSetAttribute(attn_kernel, cudaFuncAttributeMaxDynamicSharedMemorySize,
                         (int)smem_attn);

    ln_kernel <<< NTOK / 32, 256 >>>(x, ln_g, ln_b);
    gemm_qkv  <<< dim3(6, 512), 256 >>>(w_qkv);
    lepe_kernel <<< dim3(128, 128, 2), dim3(128, 4) >>>(lepe_w1, lepe_b1, lepe_w2, lepe_b2);
    attn_kernel <<< dim3(8, 2, 256), 256, smem_attn >>>();
    gemm_proj <<< dim3(2, 512), 256 >>>(proj_w, proj_b, out);
}

// round 3
// speedup vs baseline: 1.0175x; 1.0175x over previous
#include <cuda_runtime.h>
#include <math.h>

// ------------------------------------------------------------------
// Problem constants
// ------------------------------------------------------------------
#define B_    4
#define C_    256
#define H_    128
#define W_    128
#define HW    (H_*W_)          // 16384
#define NTOK  (B_*HW)          // 65536
#define CB    128
#define HEADS 2
#define CD    64
#define SCALE 0.08838834764831845f   // (256/2)^-0.5
#define EPS   1e-4f

typedef unsigned long long ull;

// packed f32x2 helpers (FFMA2 path — ptxas never auto-fuses this)
__device__ __forceinline__ ull pk2(float v) {
    ull r;
    asm("mov.b64 %0, {%1, %1};" : "=l"(r) : "f"(v));
    return r;
}
__device__ __forceinline__ void fma2(ull& d, ull a, ull b) {
    asm("fma.rn.f32x2 %0, %1, %2, %0;" : "+l"(d) : "l"(a), "l"(b));
}
__device__ __forceinline__ float2 up2(ull v) {
    float2 r;
    asm("mov.b64 {%0, %1}, %2;" : "=f"(r.x), "=f"(r.y) : "l"(v));
    return r;
}

// ------------------------------------------------------------------
// Scratch (static __device__, no allocation)
// ------------------------------------------------------------------
__device__ float g_xn [(size_t)NTOK * C_];        //  ln output, [t][c]
__device__ float g_qkv[(size_t)NTOK * 3 * C_];    //  [t][ qkv(3) br(2) head(2) d(64) ]
__device__ float g_xc [(size_t)NTOK * C_];        //  attn+lepe, [t][c] (orig channel order)

// token index of window element s for (branch, win)
__device__ __forceinline__ int win_token(int br, int win, int s) {
    int b  = win >> 5;
    int wi = win & 31;
    int y, x;
    if (br == 0) { y = s >> 2;               x = (wi << 2) + (s & 3); }   // 128x4 strip
    else         { y = (wi << 2) + (s >> 7); x = s & 127; }               // 4x128 strip
    return b * HW + y * W_ + x;
}

// ------------------------------------------------------------------
// 1) LayerNorm: x [B,C,H,W] -> g_xn [t][c]
// ------------------------------------------------------------------
__global__ void __launch_bounds__(256) ln_kernel(const float* __restrict__ x,
                                                 const float* __restrict__ gam,
                                                 const float* __restrict__ bet) {
    __shared__ float xs[C_][33];
    __shared__ float mu_s[32], rs_s[32];
    int tid = threadIdx.x;
    int tx = tid & 31, ty = tid >> 5;
    int t0 = blockIdx.x * 32;
    int b  = t0 / HW;
    int pp = t0 - b * HW;
    const float* xb = x + (size_t)b * C_ * HW + pp + tx;
    #pragma unroll
    for (int c = ty; c < C_; c += 8)
        xs[c][tx] = xb[(size_t)c * HW];
    __syncthreads();
    if (tid < 32) {
        float s = 0.f, s2 = 0.f;
        #pragma unroll 8
        for (int c = 0; c < C_; c++) { float v = xs[c][tid]; s += v; s2 += v * v; }
        float mu  = s * (1.0f / C_);
        float var = s2 * (1.0f / C_) - mu * mu;
        mu_s[tid] = mu;
        rs_s[tid] = rsqrtf(var + EPS);
    }
    __syncthreads();
    for (int idx = tid; idx < 32 * C_; idx += 256) {
        int c = idx & 255, tk = idx >> 8;
        g_xn[(size_t)(t0 + tk) * C_ + c] =
            (xs[c][tk] - mu_s[tk]) * rs_s[tk] * gam[c] + bet[c];
    }
}

// ------------------------------------------------------------------
// 2) QKV GEMM (f32x2): g_qkv[m][perm(n)] = sum_k g_xn[m][k] * W[k][n]
//    M=65536, N=768, K=256. Output columns permuted to de-interleave heads:
//    orig col = part*256 + br*128 + 2*d + head  ->  part*256 + br*128 + head*64 + d
// ------------------------------------------------------------------
__global__ void __launch_bounds__(256) gemm_qkv(const float* __restrict__ Bw) {
    __shared__ float As[8][128];
    __shared__ float Bs[8][128];
    int tid = threadIdx.x;
    int m0 = blockIdx.y * 128;
    int n0 = blockIdx.x * 128;
    int tx = tid & 15, ty = tid >> 4;
    ull acc[4][8] = {};
    int arow = tid >> 1;
    int akq  = (tid & 1) * 4;
    int brow = tid >> 5;
    int bcol = (tid & 31) * 4;
    const float* Aptr = g_xn + (size_t)(m0 + arow) * C_ + akq;
    const float* Bptr = Bw + (size_t)brow * 768 + n0 + bcol;
    for (int k0 = 0; k0 < 256; k0 += 8) {
        float4 av = *(const float4*)(Aptr + k0);
        As[akq + 0][arow] = av.x; As[akq + 1][arow] = av.y;
        As[akq + 2][arow] = av.z; As[akq + 3][arow] = av.w;
        *(float4*)&Bs[brow][bcol] = *(const float4*)(Bptr + (size_t)k0 * 768);
        __syncthreads();
        #pragma unroll
        for (int k = 0; k < 8; k++) {
            ull a2[4];
            #pragma unroll
            for (int i = 0; i < 4; i++)
                a2[i] = *(const ull*)&As[k][ty * 8 + 2 * i];
            #pragma unroll
            for (int j = 0; j < 8; j++) {
                ull b2 = pk2(Bs[k][tx + j * 16]);
                #pragma unroll
                for (int i = 0; i < 4; i++) fma2(acc[i][j], a2[i], b2);
            }
        }
        __syncthreads();
    }
    #pragma unroll
    for (int j = 0; j < 8; j++) {
        int n = n0 + tx + j * 16;
        int part = n >> 8, rm = n & 255;
        int pn = part * 256 + (rm >> 7) * 128 + ((rm & 1) << 6) + ((rm & 127) >> 1);
        size_t cb = (size_t)m0 * 768 + pn;
        #pragma unroll
        for (int i = 0; i < 4; i++) {
            float2 u = up2(acc[i][j]);
            int m = ty * 8 + 2 * i;
            g_qkv[cb + (size_t)m * 768]       = u.x;
            g_qkv[cb + (size_t)(m + 1) * 768] = u.y;
        }
    }
}

// ------------------------------------------------------------------
// 3) LePE depthwise 3x3 per strip window -> g_xc (initializes it)
//    conv channel cc maps to v column 512 + br*128 + (cc&1)*64 + (cc>>1)
// ------------------------------------------------------------------
__global__ void lepe_kernel(const float* __restrict__ w1, const float* __restrict__ b1,
                            const float* __restrict__ w2, const float* __restrict__ b2) {
    int cc  = threadIdx.x;                                  // 0..127
    int s   = blockIdx.x * blockDim.y + threadIdx.y;        // 0..511
    int win = blockIdx.y;                                   // 0..127
    int br  = blockIdx.z;                                   // 0..1
    const float* w = (br == 0 ? w1 : w2) + cc * 9;
    float bias = (br == 0 ? b1 : b2)[cc];
    int hsp = (br == 0) ? 128 : 4;
    int wsp = (br == 0) ? 4   : 128;
    int i = s / wsp, j = s % wsp;
    int vcol = 512 + br * 128 + ((cc & 1) << 6) + (cc >> 1);
    float acc = bias;
    #pragma unroll
    for (int ki = 0; ki < 3; ki++) {
        int ii = i + ki - 1;
        if (ii < 0 || ii >= hsp) continue;
        #pragma unroll
        for (int kj = 0; kj < 3; kj++) {
            int jj = j + kj - 1;
            if (jj < 0 || jj >= wsp) continue;
            int tn = win_token(br, win, ii * wsp + jj);
            acc += w[ki * 3 + kj] * g_qkv[(size_t)tn * 768 + vcol];
        }
    }
    int t = win_token(br, win, s);
    g_xc[(size_t)t * C_ + br * 128 + cc] = acc;
}

// ------------------------------------------------------------------
// 4) Attention (f32x2): per (qtile64, head, branch*win). S held in smem.
// ------------------------------------------------------------------
#define SSTR 513
#define QSTR 66
#define KSTR 257
#define VSTR 66
extern __shared__ float sm_attn[];
__global__ void __launch_bounds__(256) attn_kernel() {
    float* S   = sm_attn;               // [64][513]
    float* Qst = S + 64 * SSTR;         // [64 d][66]  (rows r)
    float* Kt  = Qst + 64 * QSTR;       // [64 d][257] (cols c) ; reused as V [128 k][66]
    int qt   = blockIdx.x;              // 0..7
    int head = blockIdx.y;              // 0..1
    int wb   = blockIdx.z;              // 0..255
    int br   = wb >> 7;
    int win  = wb & 127;
    int tid  = threadIdx.x;
    int base = br * 128 + head * 64;

    // Q^T tile, pre-scaled
    for (int idx = tid; idx < 64 * 64; idx += 256) {
        int d = idx & 63, r = idx >> 6;
        int t = win_token(br, win, qt * 64 + r);
        Qst[d * QSTR + r] = g_qkv[(size_t)t * 768 + base + d] * SCALE;
    }

    int ty = tid >> 5, tx = tid & 31;
    int r0 = ty * 8;

    // ---- S = Q K^T, two key chunks of 256 ----
    for (int kc = 0; kc < 2; kc++) {
        __syncthreads();
        for (int idx = tid; idx < 64 * 256; idx += 256) {
            int d = idx & 63, c = idx >> 6;
            int t = win_token(br, win, kc * 256 + c);
            Kt[d * KSTR + c] = g_qkv[(size_t)t * 768 + 256 + base + d];
        }
        __syncthreads();
        ull acc[4][8] = {};
        #pragma unroll 4
        for (int d = 0; d < 64; d++) {
            ull a2[4];
            #pragma unroll
            for (int i = 0; i < 4; i++)
                a2[i] = *(const ull*)&Qst[d * QSTR + r0 + 2 * i];
            #pragma unroll
            for (int j = 0; j < 8; j++) {
                ull b2 = pk2(Kt[d * KSTR + j * 32 + tx]);
                #pragma unroll
                for (int i = 0; i < 4; i++) fma2(acc[i][j], a2[i], b2);
            }
        }
        #pragma unroll
        for (int i = 0; i < 4; i++)
            #pragma unroll
            for (int j = 0; j < 8; j++) {
                float2 u = up2(acc[i][j]);
                int c = kc * 256 + j * 32 + tx;
                S[(r0 + 2 * i) * SSTR + c]     = u.x;
                S[(r0 + 2 * i + 1) * SSTR + c] = u.y;
            }
    }
    __syncthreads();

    // ---- softmax over 512 keys, one warp per 8 rows ----
    int wid = tid >> 5, lane = tid & 31;
    for (int r = wid * 8; r < wid * 8 + 8; r++) {
        float* row = S + r * SSTR;
        float m = -1e30f;
        for (int c = lane; c < 512; c += 32) m = fmaxf(m, row[c]);
        #pragma unroll
        for (int o = 16; o; o >>= 1) m = fmaxf(m, __shfl_xor_sync(0xffffffffu, m, o));
        float ssum = 0.f;
        for (int c = lane; c < 512; c += 32) {
            float e = __expf(row[c] - m);
            row[c] = e;
            ssum += e;
        }
        #pragma unroll
        for (int o = 16; o; o >>= 1) ssum += __shfl_xor_sync(0xffffffffu, ssum, o);
        float inv = 1.0f / ssum;
        for (int c = lane; c < 512; c += 32) row[c] *= inv;
    }

    // ---- O = P V, V chunks of 128 rows (reuse Kt region) ----
    int txd = tid & 15, tyq = tid >> 4;
    int rq = tyq * 4, d0 = txd * 4;
    ull o2[4][2] = {};
    for (int vt = 0; vt < 4; vt++) {
        __syncthreads();
        for (int idx = tid; idx < 128 * 64; idx += 256) {
            int d = idx & 63, kk = idx >> 6;
            int t = win_token(br, win, vt * 128 + kk);
            Kt[kk * VSTR + d] = g_qkv[(size_t)t * 768 + 512 + base + d];
        }
        __syncthreads();
        #pragma unroll 4
        for (int k = 0; k < 128; k++) {
            ull v0 = *(const ull*)&Kt[k * VSTR + d0];
            ull v1 = *(const ull*)&Kt[k * VSTR + d0 + 2];
            #pragma unroll
            for (int i = 0; i < 4; i++) {
                ull p2 = pk2(S[(rq + i) * SSTR + vt * 128 + k]);
                fma2(o2[i][0], p2, v0);
                fma2(o2[i][1], p2, v1);
            }
        }
    }

    // accumulate on top of LePE (disjoint elements per block)
    #pragma unroll
    for (int i = 0; i < 4; i++) {
        int t = win_token(br, win, qt * 64 + rq + i);
        size_t gb = (size_t)t * C_ + br * 128 + head;
        #pragma unroll
        for (int jp = 0; jp < 2; jp++) {
            float2 u = up2(o2[i][jp]);
            g_xc[gb + 2 * (d0 + 2 * jp)]     += u.x;
            g_xc[gb + 2 * (d0 + 2 * jp + 1)] += u.y;
        }
    }
}

// ------------------------------------------------------------------
// 5) Proj GEMM (f32x2): out[b,o,y,x] = sum_c g_xc[t][c] * proj_w[o][c] + proj_b[o]
// ------------------------------------------------------------------
__global__ void __launch_bounds__(256) gemm_proj(const float* __restrict__ Pw,
                                                 const float* __restrict__ Pb,
                                                 float* __restrict__ out) {
    __shared__ float As[8][128];
    __shared__ float Bs[8][129];
    int tid = threadIdx.x;
    int m0 = blockIdx.y * 128;
    int n0 = blockIdx.x * 128;
    int tx = tid & 15, ty = tid >> 4;
    ull acc[4][8] = {};   // pairs along m: m = ty*8 + 2i (+1), n = tx + j*16
    int arow = tid >> 1;
    int akq  = (tid & 1) * 4;
    const float* Aptr = g_xc + (size_t)(m0 + arow) * C_ + akq;
    int bn  = tid >> 1;
    int bkq = (tid & 1) * 4;
    const float* Bptr = Pw + (size_t)(n0 + bn) * C_ + bkq;
    for (int k0 = 0; k0 < 256; k0 += 8) {
        float4 av = *(const float4*)(Aptr + k0);
        As[akq + 0][arow] = av.x; As[akq + 1][arow] = av.y;
        As[akq + 2][arow] = av.z; As[akq + 3][arow] = av.w;
        float4 bv = *(const float4*)(Bptr + k0);
        Bs[bkq + 0][bn] = bv.x; Bs[bkq + 1][bn] = bv.y;
        Bs[bkq + 2][bn] = bv.z; Bs[bkq + 3][bn] = bv.w;
        __syncthreads();
        #pragma unroll
        for (int k = 0; k < 8; k++) {
            ull a2[4];
            #pragma unroll
            for (int i = 0; i < 4; i++)
                a2[i] = *(const ull*)&As[k][ty * 8 + 2 * i];
            #pragma unroll
            for (int j = 0; j < 8; j++) {
                ull b2 = pk2(Bs[k][tx + j * 16]);
                #pragma unroll
                for (int i = 0; i < 4; i++) fma2(acc[i][j], a2[i], b2);
            }
        }
        __syncthreads();
    }
    int b  = m0 / HW;
    int pp = m0 - b * HW;
    float* Op = out + (size_t)b * C_ * HW + pp;
    #pragma unroll
    for (int j = 0; j < 8; j++) {
        int o = n0 + tx + j * 16;
        float bias = Pb[o];
        #pragma unroll
        for (int i = 0; i < 4; i++) {
            float2 u = up2(acc[i][j]);
            float2 w = make_float2(u.x + bias, u.y + bias);
            *(float2*)&Op[(size_t)o * HW + ty * 8 + 2 * i] = w;
        }
    }
}

// ------------------------------------------------------------------
// launch
// ------------------------------------------------------------------
extern "C" void kernel_launch(void* const* d_in, const int* in_sizes, int n_in,
                              void* d_out, int out_size) {
    const float* x       = (const float*)d_in[0];
    const float* ln_g    = (const float*)d_in[1];
    const float* ln_b    = (const float*)d_in[2];
    const float* w_qkv   = (const float*)d_in[3];
    const float* lepe_w1 = (const float*)d_in[4];
    const float* lepe_b1 = (const float*)d_in[5];
    const float* lepe_w2 = (const float*)d_in[6];
    const float* lepe_b2 = (const float*)d_in[7];
    const float* proj_w  = (const float*)d_in[8];
    const float* proj_b  = (const float*)d_in[9];
    float* out = (float*)d_out;

    size_t smem_attn = (size_t)(64 * SSTR + 64 * QSTR + 64 * KSTR) * sizeof(float); // 214,016 B
    cudaFuncSetAttribute(attn_kernel, cudaFuncAttributeMaxDynamicSharedMemorySize,
                         (int)smem_attn);

    ln_kernel <<< NTOK / 32, 256 >>>(x, ln_g, ln_b);
    gemm_qkv  <<< dim3(6, 512), 256 >>>(w_qkv);
    lepe_kernel <<< dim3(128, 128, 2), dim3(128, 4) >>>(lepe_w1, lepe_b1, lepe_w2, lepe_b2);
    attn_kernel <<< dim3(8, 2, 256), 256, smem_attn >>>();
    gemm_proj <<< dim3(2, 512), 256 >>>(proj_w, proj_b, out);
}

// round 4
// speedup vs baseline: 1.2097x; 1.1888x over previous
#include <cuda_runtime.h>
#include <math.h>

// ------------------------------------------------------------------
// Problem constants
// ------------------------------------------------------------------
#define B_    4
#define C_    256
#define H_    128
#define W_    128
#define HW    (H_*W_)          // 16384
#define NTOK  (B_*HW)          // 65536
#define CB    128
#define HEADS 2
#define CD    64
#define SCALE 0.08838834764831845f   // (256/2)^-0.5
#define EPS   1e-4f

typedef unsigned long long ull;

// packed f32x2 helpers (FFMA2 path — ptxas never auto-fuses this)
__device__ __forceinline__ ull pk2(float v) {
    ull r;
    asm("mov.b64 %0, {%1, %1};" : "=l"(r) : "f"(v));
    return r;
}
__device__ __forceinline__ void fma2(ull& d, ull a, ull b) {
    asm("fma.rn.f32x2 %0, %1, %2, %0;" : "+l"(d) : "l"(a), "l"(b));
}
__device__ __forceinline__ void add2(ull& d, ull a) {
    asm("add.rn.f32x2 %0, %0, %1;" : "+l"(d) : "l"(a));
}
__device__ __forceinline__ float2 up2(ull v) {
    float2 r;
    asm("mov.b64 {%0, %1}, %2;" : "=f"(r.x), "=f"(r.y) : "l"(v));
    return r;
}

// ------------------------------------------------------------------
// Scratch (static __device__, no allocation)
// ------------------------------------------------------------------
__device__ float g_xn [(size_t)NTOK * C_];        //  ln output, [t][c]
__device__ float g_qkv[(size_t)NTOK * 3 * C_];    //  [t][ qkv(3) br(2) head(2) d(64) ]
__device__ float g_xc [(size_t)NTOK * C_];        //  attn+lepe, [t][c] (orig channel order)

// token index of window element s for (branch, win)
__device__ __forceinline__ int win_token(int br, int win, int s) {
    int b  = win >> 5;
    int wi = win & 31;
    int y, x;
    if (br == 0) { y = s >> 2;               x = (wi << 2) + (s & 3); }   // 128x4 strip
    else         { y = (wi << 2) + (s >> 7); x = s & 127; }               // 4x128 strip
    return b * HW + y * W_ + x;
}

// ------------------------------------------------------------------
// 1) LayerNorm: x [B,C,H,W] -> g_xn [t][c]
// ------------------------------------------------------------------
__global__ void __launch_bounds__(256) ln_kernel(const float* __restrict__ x,
                                                 const float* __restrict__ gam,
                                                 const float* __restrict__ bet) {
    __shared__ float xs[C_][33];
    __shared__ float mu_s[32], rs_s[32];
    int tid = threadIdx.x;
    int tx = tid & 31, ty = tid >> 5;
    int t0 = blockIdx.x * 32;
    int b  = t0 / HW;
    int pp = t0 - b * HW;
    const float* xb = x + (size_t)b * C_ * HW + pp + tx;
    #pragma unroll
    for (int c = ty; c < C_; c += 8)
        xs[c][tx] = xb[(size_t)c * HW];
    __syncthreads();
    if (tid < 32) {
        float s = 0.f, s2 = 0.f;
        #pragma unroll 8
        for (int c = 0; c < C_; c++) { float v = xs[c][tid]; s += v; s2 += v * v; }
        float mu  = s * (1.0f / C_);
        float var = s2 * (1.0f / C_) - mu * mu;
        mu_s[tid] = mu;
        rs_s[tid] = rsqrtf(var + EPS);
    }
    __syncthreads();
    for (int idx = tid; idx < 32 * C_; idx += 256) {
        int c = idx & 255, tk = idx >> 8;
        g_xn[(size_t)(t0 + tk) * C_ + c] =
            (xs[c][tk] - mu_s[tk]) * rs_s[tk] * gam[c] + bet[c];
    }
}

// ------------------------------------------------------------------
// 2) QKV GEMM (f32x2): g_qkv[m][perm(n)] = sum_k g_xn[m][k] * W[k][n]
//    M=65536, N=768, K=256. Output columns permuted to de-interleave heads:
//    orig col = part*256 + br*128 + 2*d + head  ->  part*256 + br*128 + head*64 + d
// ------------------------------------------------------------------
__global__ void __launch_bounds__(256) gemm_qkv(const float* __restrict__ Bw) {
    __shared__ float As[8][128];
    __shared__ float Bs[8][128];
    int tid = threadIdx.x;
    int m0 = blockIdx.y * 128;
    int n0 = blockIdx.x * 128;
    int tx = tid & 15, ty = tid >> 4;
    ull acc[4][8] = {};
    int arow = tid >> 1;
    int akq  = (tid & 1) * 4;
    int brow = tid >> 5;
    int bcol = (tid & 31) * 4;
    const float* Aptr = g_xn + (size_t)(m0 + arow) * C_ + akq;
    const float* Bptr = Bw + (size_t)brow * 768 + n0 + bcol;
    for (int k0 = 0; k0 < 256; k0 += 8) {
        float4 av = *(const float4*)(Aptr + k0);
        As[akq + 0][arow] = av.x; As[akq + 1][arow] = av.y;
        As[akq + 2][arow] = av.z; As[akq + 3][arow] = av.w;
        *(float4*)&Bs[brow][bcol] = *(const float4*)(Bptr + (size_t)k0 * 768);
        __syncthreads();
        #pragma unroll
        for (int k = 0; k < 8; k++) {
            ull a2[4];
            #pragma unroll
            for (int i = 0; i < 4; i++)
                a2[i] = *(const ull*)&As[k][ty * 8 + 2 * i];
            #pragma unroll
            for (int j = 0; j < 8; j++) {
                ull b2 = pk2(Bs[k][tx + j * 16]);
                #pragma unroll
                for (int i = 0; i < 4; i++) fma2(acc[i][j], a2[i], b2);
            }
        }
        __syncthreads();
    }
    #pragma unroll
    for (int j = 0; j < 8; j++) {
        int n = n0 + tx + j * 16;
        int part = n >> 8, rm = n & 255;
        int pn = part * 256 + (rm >> 7) * 128 + ((rm & 1) << 6) + ((rm & 127) >> 1);
        size_t cb = (size_t)m0 * 768 + pn;
        #pragma unroll
        for (int i = 0; i < 4; i++) {
            float2 u = up2(acc[i][j]);
            int m = ty * 8 + 2 * i;
            g_qkv[cb + (size_t)m * 768]       = u.x;
            g_qkv[cb + (size_t)(m + 1) * 768] = u.y;
        }
    }
}

// ------------------------------------------------------------------
// 3) LePE depthwise 3x3 per strip window -> g_xc (initializes it)
//    conv channel cc maps to v column 512 + br*128 + (cc&1)*64 + (cc>>1)
// ------------------------------------------------------------------
__global__ void lepe_kernel(const float* __restrict__ w1, const float* __restrict__ b1,
                            const float* __restrict__ w2, const float* __restrict__ b2) {
    int cc  = threadIdx.x;                                  // 0..127
    int s   = blockIdx.x * blockDim.y + threadIdx.y;        // 0..511
    int win = blockIdx.y;                                   // 0..127
    int br  = blockIdx.z;                                   // 0..1
    const float* w = (br == 0 ? w1 : w2) + cc * 9;
    float bias = (br == 0 ? b1 : b2)[cc];
    int hsp = (br == 0) ? 128 : 4;
    int wsp = (br == 0) ? 4   : 128;
    int i = s / wsp, j = s % wsp;
    int vcol = 512 + br * 128 + ((cc & 1) << 6) + (cc >> 1);
    float acc = bias;
    #pragma unroll
    for (int ki = 0; ki < 3; ki++) {
        int ii = i + ki - 1;
        if (ii < 0 || ii >= hsp) continue;
        #pragma unroll
        for (int kj = 0; kj < 3; kj++) {
            int jj = j + kj - 1;
            if (jj < 0 || jj >= wsp) continue;
            int tn = win_token(br, win, ii * wsp + jj);
            acc += w[ki * 3 + kj] * g_qkv[(size_t)tn * 768 + vcol];
        }
    }
    int t = win_token(br, win, s);
    g_xc[(size_t)t * C_ + br * 128 + cc] = acc;
}

// ------------------------------------------------------------------
// 4) Attention (f32x2, 512 threads): per (qtile64, head, branch*win).
//    QK: 16 warps tile 64x256 chunk as 8 row-groups x 2 col-halves.
//    PV: k-sum split across thread halves with double-buffered V chunks,
//        followed by a smem pair-reduction.
// ------------------------------------------------------------------
#define SSTR 513
#define QSTR 66
#define KSTR 257
#define VSTR 66
extern __shared__ float sm_attn[];
__global__ void __launch_bounds__(512) attn_kernel() {
    float* S   = sm_attn;               // [64][513]
    float* Qst = S + 64 * SSTR;         // [64 d][66]  (Q^T)
    float* Kt  = Qst + 64 * QSTR;       // [64 d][257] (K^T chunk)
    float* VA  = Qst;                   // PV phase: [128 k][66]
    float* VB  = VA + 128 * VSTR;       // second V chunk
    int qt   = blockIdx.x;              // 0..7
    int head = blockIdx.y;              // 0..1
    int wb   = blockIdx.z;              // 0..255
    int br   = wb >> 7;
    int win  = wb & 127;
    int tid  = threadIdx.x;
    int base = br * 128 + head * 64;

    // Q^T tile, pre-scaled
    for (int idx = tid; idx < 64 * 64; idx += 512) {
        int d = idx & 63, r = idx >> 6;
        int t = win_token(br, win, qt * 64 + r);
        Qst[d * QSTR + r] = g_qkv[(size_t)t * 768 + base + d] * SCALE;
    }

    int w    = tid >> 5, lane = tid & 31;
    int r0   = (w & 7) * 8;             // row group
    int ch   = w >> 3;                  // column half (0/1) of the 256-chunk

    // ---- S = Q K^T, two key chunks of 256 ----
    for (int kc = 0; kc < 2; kc++) {
        __syncthreads();
        for (int idx = tid; idx < 64 * 256; idx += 512) {
            int d = idx & 63, c = idx >> 6;
            int t = win_token(br, win, kc * 256 + c);
            Kt[d * KSTR + c] = g_qkv[(size_t)t * 768 + 256 + base + d];
        }
        __syncthreads();
        ull acc[4][4] = {};
        #pragma unroll 4
        for (int d = 0; d < 64; d++) {
            ull a2[4];
            #pragma unroll
            for (int i = 0; i < 4; i++)
                a2[i] = *(const ull*)&Qst[d * QSTR + r0 + 2 * i];
            #pragma unroll
            for (int j = 0; j < 4; j++) {
                ull b2 = pk2(Kt[d * KSTR + ch * 128 + j * 32 + lane]);
                #pragma unroll
                for (int i = 0; i < 4; i++) fma2(acc[i][j], a2[i], b2);
            }
        }
        #pragma unroll
        for (int i = 0; i < 4; i++)
            #pragma unroll
            for (int j = 0; j < 4; j++) {
                float2 u = up2(acc[i][j]);
                int c = kc * 256 + ch * 128 + j * 32 + lane;
                S[(r0 + 2 * i) * SSTR + c]     = u.x;
                S[(r0 + 2 * i + 1) * SSTR + c] = u.y;
            }
    }
    __syncthreads();

    // ---- softmax over 512 keys, one warp per 4 rows ----
    for (int r = w * 4; r < w * 4 + 4; r++) {
        float* row = S + r * SSTR;
        float m = -1e30f;
        for (int c = lane; c < 512; c += 32) m = fmaxf(m, row[c]);
        #pragma unroll
        for (int o = 16; o; o >>= 1) m = fmaxf(m, __shfl_xor_sync(0xffffffffu, m, o));
        float ssum = 0.f;
        for (int c = lane; c < 512; c += 32) {
            float e = __expf(row[c] - m);
            row[c] = e;
            ssum += e;
        }
        #pragma unroll
        for (int o = 16; o; o >>= 1) ssum += __shfl_xor_sync(0xffffffffu, ssum, o);
        float inv = 1.0f / ssum;
        for (int c = lane; c < 512; c += 32) row[c] *= inv;
    }

    // ---- O = P V, k-split across thread halves, double-buffered V ----
    int b8  = tid & 255;                // base thread id within a half
    int h   = tid >> 8;                 // k-half (0/1)
    int txd = b8 & 15, tyq = b8 >> 4;
    int rq  = tyq * 4, d0 = txd * 4;
    ull o2[4][2] = {};
    for (int vtp = 0; vtp < 2; vtp++) {
        __syncthreads();
        // load V chunks vtp*2 (->VA) and vtp*2+1 (->VB)
        for (int idx = tid; idx < 2 * 128 * 64; idx += 512) {
            int d = idx & 63, kk = (idx >> 6) & 127;
            int cidx = idx >> 13;       // 0 or 1
            int t = win_token(br, win, (vtp * 2 + cidx) * 128 + kk);
            float* dst = cidx ? VB : VA;
            dst[kk * VSTR + d] = g_qkv[(size_t)t * 768 + 512 + base + d];
        }
        __syncthreads();
        const float* Vm = h ? VB : VA;
        int koff = (vtp * 2 + h) * 128;
        #pragma unroll 4
        for (int k = 0; k < 128; k++) {
            ull v0 = *(const ull*)&Vm[k * VSTR + d0];
            ull v1 = *(const ull*)&Vm[k * VSTR + d0 + 2];
            #pragma unroll
            for (int i = 0; i < 4; i++) {
                ull p2 = pk2(S[(rq + i) * SSTR + koff + k]);
                fma2(o2[i][0], p2, v0);
                fma2(o2[i][1], p2, v1);
            }
        }
    }

    // ---- pair reduction (half 1 -> half 0) via smem (reuse S region) ----
    ull* red = (ull*)S;                 // 256 x 8 ull = 16 KB
    __syncthreads();
    if (h == 1) {
        #pragma unroll
        for (int i = 0; i < 4; i++) {
            red[b8 * 8 + 2 * i]     = o2[i][0];
            red[b8 * 8 + 2 * i + 1] = o2[i][1];
        }
    }
    __syncthreads();
    if (h == 0) {
        #pragma unroll
        for (int i = 0; i < 4; i++) {
            add2(o2[i][0], red[b8 * 8 + 2 * i]);
            add2(o2[i][1], red[b8 * 8 + 2 * i + 1]);
        }
        // accumulate on top of LePE (disjoint elements per block)
        #pragma unroll
        for (int i = 0; i < 4; i++) {
            int t = win_token(br, win, qt * 64 + rq + i);
            size_t gb = (size_t)t * C_ + br * 128 + head;
            #pragma unroll
            for (int jp = 0; jp < 2; jp++) {
                float2 u = up2(o2[i][jp]);
                g_xc[gb + 2 * (d0 + 2 * jp)]     += u.x;
                g_xc[gb + 2 * (d0 + 2 * jp + 1)] += u.y;
            }
        }
    }
}

// ------------------------------------------------------------------
// 5) Proj GEMM (f32x2): out[b,o,y,x] = sum_c g_xc[t][c] * proj_w[o][c] + proj_b[o]
// ------------------------------------------------------------------
__global__ void __launch_bounds__(256) gemm_proj(const float* __restrict__ Pw,
                                                 const float* __restrict__ Pb,
                                                 float* __restrict__ out) {
    __shared__ float As[8][128];
    __shared__ float Bs[8][129];
    int tid = threadIdx.x;
    int m0 = blockIdx.y * 128;
    int n0 = blockIdx.x * 128;
    int tx = tid & 15, ty = tid >> 4;
    ull acc[4][8] = {};   // pairs along m: m = ty*8 + 2i (+1), n = tx + j*16
    int arow = tid >> 1;
    int akq  = (tid & 1) * 4;
    const float* Aptr = g_xc + (size_t)(m0 + arow) * C_ + akq;
    int bn  = tid >> 1;
    int bkq = (tid & 1) * 4;
    const float* Bptr = Pw + (size_t)(n0 + bn) * C_ + bkq;
    for (int k0 = 0; k0 < 256; k0 += 8) {
        float4 av = *(const float4*)(Aptr + k0);
        As[akq + 0][arow] = av.x; As[akq + 1][arow] = av.y;
        As[akq + 2][arow] = av.z; As[akq + 3][arow] = av.w;
        float4 bv = *(const float4*)(Bptr + k0);
        Bs[bkq + 0][bn] = bv.x; Bs[bkq + 1][bn] = bv.y;
        Bs[bkq + 2][bn] = bv.z; Bs[bkq + 3][bn] = bv.w;
        __syncthreads();
        #pragma unroll
        for (int k = 0; k < 8; k++) {
            ull a2[4];
            #pragma unroll
            for (int i = 0; i < 4; i++)
                a2[i] = *(const ull*)&As[k][ty * 8 + 2 * i];
            #pragma unroll
            for (int j = 0; j < 8; j++) {
                ull b2 = pk2(Bs[k][tx + j * 16]);
                #pragma unroll
                for (int i = 0; i < 4; i++) fma2(acc[i][j], a2[i], b2);
            }
        }
        __syncthreads();
    }
    int b  = m0 / HW;
    int pp = m0 - b * HW;
    float* Op = out + (size_t)b * C_ * HW + pp;
    #pragma unroll
    for (int j = 0; j < 8; j++) {
        int o = n0 + tx + j * 16;
        float bias = Pb[o];
        #pragma unroll
        for (int i = 0; i < 4; i++) {
            float2 u = up2(acc[i][j]);
            float2 w = make_float2(u.x + bias, u.y + bias);
            *(float2*)&Op[(size_t)o * HW + ty * 8 + 2 * i] = w;
        }
    }
}

// ------------------------------------------------------------------
// launch
// ------------------------------------------------------------------
extern "C" void kernel_launch(void* const* d_in, const int* in_sizes, int n_in,
                              void* d_out, int out_size) {
    const float* x       = (const float*)d_in[0];
    const float* ln_g    = (const float*)d_in[1];
    const float* ln_b    = (const float*)d_in[2];
    const float* w_qkv   = (const float*)d_in[3];
    const float* lepe_w1 = (const float*)d_in[4];
    const float* lepe_b1 = (const float*)d_in[5];
    const float* lepe_w2 = (const float*)d_in[6];
    const float* lepe_b2 = (const float*)d_in[7];
    const float* proj_w  = (const float*)d_in[8];
    const float* proj_b  = (const float*)d_in[9];
    float* out = (float*)d_out;

    size_t smem_attn = (size_t)(64 * SSTR + 64 * QSTR + 64 * KSTR) * sizeof(float); // 214,016 B
    cudaFuncSetAttribute(attn_kernel, cudaFuncAttributeMaxDynamicSharedMemorySize,
                         (int)smem_attn);

    ln_kernel <<< NTOK / 32, 256 >>>(x, ln_g, ln_b);
    gemm_qkv  <<< dim3(6, 512), 256 >>>(w_qkv);
    lepe_kernel <<< dim3(128, 128, 2), dim3(128, 4) >>>(lepe_w1, lepe_b1, lepe_w2, lepe_b2);
    attn_kernel <<< dim3(8, 2, 256), 512, smem_attn >>>();
    gemm_proj <<< dim3(2, 512), 256 >>>(proj_w, proj_b, out);
}